// round 2
// baseline (speedup 1.0000x reference)
#include <cuda_runtime.h>
#include <cuda_bf16.h>
#include <math.h>

// Problem constants
#define B_  2
#define S_  2048
#define DIM_ 4096
#define HQ_ 32
#define HKV_ 8
#define HD_ 128
#define NREP_ 4   // HQ/HKV

// -------------------- scratch (device globals, no allocation) ---------------
__device__ float g_q[(size_t)B_ * S_ * HQ_ * HD_];    // 64 MB  [token][HQ*HD]
__device__ float g_k[(size_t)B_ * S_ * HKV_ * HD_];   // 16 MB  [token][HKV*HD]
__device__ float g_v[(size_t)B_ * S_ * HKV_ * HD_];   // 16 MB
__device__ float g_attn[(size_t)B_ * S_ * HQ_ * HD_]; // 64 MB  [token][HQ*HD]

// ======================= Generic NT SGEMM ===================================
// C[M,N] = A[M,K] * B[N,K]^T (+ bias[N]).  A,B row-major, K-contiguous.
// 128x128 tile, BK=16, 256 threads, 8x8 micro-tile.
#define GBM 128
#define GBN 128
#define GBK 16

__global__ __launch_bounds__(256) void sgemm_nt(
    const float* __restrict__ A, const float* __restrict__ Bm,
    const float* __restrict__ bias, float* __restrict__ C,
    int M, int N, int K)
{
    __shared__ float As[GBK][GBM];
    __shared__ float Bs[GBK][GBN];

    const int tid = threadIdx.x;
    const int tx = tid & 15;       // 0..15 -> N
    const int ty = tid >> 4;       // 0..15 -> M
    const int m0 = blockIdx.y * GBM;
    const int n0 = blockIdx.x * GBN;

    float acc[8][8];
#pragma unroll
    for (int i = 0; i < 8; i++)
#pragma unroll
        for (int j = 0; j < 8; j++) acc[i][j] = 0.f;

    for (int k0 = 0; k0 < K; k0 += GBK) {
        // load tiles (512 float4 each, 2 per thread)
#pragma unroll
        for (int r = 0; r < 2; r++) {
            int idx = tid + r * 256;
            int row = idx >> 2;
            int c4  = (idx & 3) * 4;
            float4 a = *(const float4*)(A + (size_t)(m0 + row) * K + k0 + c4);
            As[c4 + 0][row] = a.x; As[c4 + 1][row] = a.y;
            As[c4 + 2][row] = a.z; As[c4 + 3][row] = a.w;
            float4 b = *(const float4*)(Bm + (size_t)(n0 + row) * K + k0 + c4);
            Bs[c4 + 0][row] = b.x; Bs[c4 + 1][row] = b.y;
            Bs[c4 + 2][row] = b.z; Bs[c4 + 3][row] = b.w;
        }
        __syncthreads();

#pragma unroll
        for (int k = 0; k < GBK; k++) {
            float ar[8], br[8];
            *(float4*)&ar[0] = *(const float4*)&As[k][ty * 8];
            *(float4*)&ar[4] = *(const float4*)&As[k][ty * 8 + 4];
            *(float4*)&br[0] = *(const float4*)&Bs[k][tx * 8];
            *(float4*)&br[4] = *(const float4*)&Bs[k][tx * 8 + 4];
#pragma unroll
            for (int i = 0; i < 8; i++)
#pragma unroll
                for (int j = 0; j < 8; j++)
                    acc[i][j] += ar[i] * br[j];
        }
        __syncthreads();
    }

    // epilogue
#pragma unroll
    for (int i = 0; i < 8; i++) {
        int m = m0 + ty * 8 + i;
        float* crow = C + (size_t)m * N + n0 + tx * 8;
        float bv[8];
#pragma unroll
        for (int j = 0; j < 8; j++)
            bv[j] = bias ? bias[n0 + tx * 8 + j] : 0.f;
        float4 v0 = make_float4(acc[i][0] + bv[0], acc[i][1] + bv[1],
                                acc[i][2] + bv[2], acc[i][3] + bv[3]);
        float4 v1 = make_float4(acc[i][4] + bv[4], acc[i][5] + bv[5],
                                acc[i][6] + bv[6], acc[i][7] + bv[7]);
        *(float4*)crow = v0;
        *(float4*)(crow + 4) = v1;
    }
}

// ======================= RoPE (in place) ====================================
// x: [token][H*HD]; grid.x = B*S*H, 64 threads handle pairs (d, d+64).
__global__ void rope_kernel(float* __restrict__ xh,
                            const float* __restrict__ cosT,
                            const float* __restrict__ sinT, int H)
{
    int idx = blockIdx.x;            // token*H + h
    int token = idx / H;
    int s = token % S_;
    float* p = xh + (size_t)idx * HD_;
    int d = threadIdx.x;             // 0..63
    float c0 = cosT[s * HD_ + d];
    float s0 = sinT[s * HD_ + d];
    float c1 = cosT[s * HD_ + d + 64];
    float s1 = sinT[s * HD_ + d + 64];
    float x0 = p[d];
    float x1 = p[d + 64];
    p[d]      = x0 * c0 - x1 * s0;
    p[d + 64] = x1 * c1 + x0 * s1;
}

// ======================= Flash attention (fp32) =============================
// Per block: 64 query rows of one (b,h). 256 threads (16x16).
// Smem: Qs[64][128] | KVs[64][128] (K swizzled f4 / V linear f4) | Ps[64][64]
#define ATTN_SMEM_BYTES ((64 * 128 + 64 * 128 + 64 * 64) * 4)

__global__ __launch_bounds__(256) void attn_kernel(
    const float* __restrict__ Q, const float* __restrict__ Kg,
    const float* __restrict__ Vg, float* __restrict__ O)
{
    extern __shared__ float smem[];
    float* Qs  = smem;                 // 64*128
    float* KVs = smem + 64 * 128;      // 64*128 (K then V)
    float* Ps  = smem + 2 * 64 * 128;  // 64*64

    const int qt = blockIdx.x;
    const int bh = blockIdx.y;
    const int b  = bh / HQ_;
    const int h  = bh % HQ_;
    const int kh = h / NREP_;

    const int tid = threadIdx.x;
    const int tx = tid & 15;
    const int ty = tid >> 4;

    const float scaling = 0.08838834764831845f;  // 1/sqrt(128)

    // load Q tile (rows = queries, 128 f each)
    const float* qbase = Q + ((size_t)(b * S_ + qt * 64) * HQ_ + h) * HD_;
#pragma unroll
    for (int r = 0; r < 8; r++) {
        int idx = tid + r * 256;
        int row = idx >> 5;
        int c4  = idx & 31;
        float4 v = *(const float4*)(qbase + (size_t)row * HQ_ * HD_ + c4 * 4);
        *(float4*)&Qs[row * 128 + c4 * 4] = v;
    }

    float m_i[4], l_i[4], o_acc[4][8];
#pragma unroll
    for (int i = 0; i < 4; i++) {
        m_i[i] = -1e30f;
        l_i[i] = 0.f;
#pragma unroll
        for (int j = 0; j < 8; j++) o_acc[i][j] = 0.f;
    }
    __syncthreads();

    const float* kbase = Kg + (size_t)b * S_ * HKV_ * HD_ + (size_t)kh * HD_;
    const float* vbase = Vg + (size_t)b * S_ * HKV_ * HD_ + (size_t)kh * HD_;
    float4* K4 = (float4*)KVs;
    float4* V4 = (float4*)KVs;

    for (int kt = 0; kt <= qt; kt++) {
        // ---- load K tile, transposed-swizzled: K4[col][k4 ^ (col&31)] ----
#pragma unroll
        for (int r = 0; r < 8; r++) {
            int idx = tid + r * 256;
            int col = idx >> 5;      // kv row within tile
            int k4  = idx & 31;      // float4 index along HD
            float4 v = *(const float4*)(kbase +
                        (size_t)(kt * 64 + col) * HKV_ * HD_ + k4 * 4);
            K4[col * 32 + (k4 ^ (col & 31))] = v;
        }
        __syncthreads();

        // ---- scores S = Q K^T  (4x4 per thread) ----
        float sacc[4][4];
#pragma unroll
        for (int i = 0; i < 4; i++)
#pragma unroll
            for (int j = 0; j < 4; j++) sacc[i][j] = 0.f;

#pragma unroll 4
        for (int k4 = 0; k4 < 32; k4++) {
            float4 a[4], bb[4];
#pragma unroll
            for (int i = 0; i < 4; i++)
                a[i] = *(const float4*)&Qs[(ty * 4 + i) * 128 + k4 * 4];
#pragma unroll
            for (int j = 0; j < 4; j++) {
                int col = tx * 4 + j;
                bb[j] = K4[col * 32 + (k4 ^ (col & 31))];
            }
#pragma unroll
            for (int i = 0; i < 4; i++)
#pragma unroll
                for (int j = 0; j < 4; j++)
                    sacc[i][j] += a[i].x * bb[j].x + a[i].y * bb[j].y +
                                  a[i].z * bb[j].z + a[i].w * bb[j].w;
        }

        // ---- scale + causal mask ----
        const bool diag = (kt == qt);
#pragma unroll
        for (int i = 0; i < 4; i++)
#pragma unroll
            for (int j = 0; j < 4; j++) {
                float s = sacc[i][j] * scaling;
                if (diag && (tx * 4 + j) > (ty * 4 + i)) s = -1e30f;
                sacc[i][j] = s;
            }

        // ---- online softmax (reduce across 16-thread row group) ----
#pragma unroll
        for (int i = 0; i < 4; i++) {
            float rmax = fmaxf(fmaxf(sacc[i][0], sacc[i][1]),
                               fmaxf(sacc[i][2], sacc[i][3]));
#pragma unroll
            for (int off = 8; off; off >>= 1)
                rmax = fmaxf(rmax, __shfl_xor_sync(0xffffffffu, rmax, off));
            float mnew = fmaxf(m_i[i], rmax);
            float corr = __expf(m_i[i] - mnew);
            m_i[i] = mnew;
            float rsum = 0.f;
#pragma unroll
            for (int j = 0; j < 4; j++) {
                float p = __expf(sacc[i][j] - mnew);
                sacc[i][j] = p;
                rsum += p;
            }
#pragma unroll
            for (int off = 8; off; off >>= 1)
                rsum += __shfl_xor_sync(0xffffffffu, rsum, off);
            l_i[i] = l_i[i] * corr + rsum;
#pragma unroll
            for (int j = 0; j < 8; j++) o_acc[i][j] *= corr;
            *(float4*)&Ps[(ty * 4 + i) * 64 + tx * 4] =
                make_float4(sacc[i][0], sacc[i][1], sacc[i][2], sacc[i][3]);
        }
        __syncthreads();   // P written; K reads done

        // ---- load V tile (linear f4 layout) ----
#pragma unroll
        for (int r = 0; r < 8; r++) {
            int idx = tid + r * 256;
            int row = idx >> 5;
            int c4  = idx & 31;
            V4[row * 32 + c4] = *(const float4*)(vbase +
                        (size_t)(kt * 64 + row) * HKV_ * HD_ + c4 * 4);
        }
        __syncthreads();

        // ---- O += P V ----
#pragma unroll 4
        for (int kk = 0; kk < 64; kk++) {
            float p0 = Ps[(ty * 4 + 0) * 64 + kk];
            float p1 = Ps[(ty * 4 + 1) * 64 + kk];
            float p2 = Ps[(ty * 4 + 2) * 64 + kk];
            float p3 = Ps[(ty * 4 + 3) * 64 + kk];
            float4 v0 = V4[kk * 32 + tx * 2];
            float4 v1 = V4[kk * 32 + tx * 2 + 1];
            float pv[4] = {p0, p1, p2, p3};
#pragma unroll
            for (int i = 0; i < 4; i++) {
                o_acc[i][0] += pv[i] * v0.x; o_acc[i][1] += pv[i] * v0.y;
                o_acc[i][2] += pv[i] * v0.z; o_acc[i][3] += pv[i] * v0.w;
                o_acc[i][4] += pv[i] * v1.x; o_acc[i][5] += pv[i] * v1.y;
                o_acc[i][6] += pv[i] * v1.z; o_acc[i][7] += pv[i] * v1.w;
            }
        }
        __syncthreads();   // V reads done before next K overwrite
    }

    // ---- epilogue: normalize + write [b,s,h,hd] ----
#pragma unroll
    for (int i = 0; i < 4; i++) {
        float inv = 1.f / l_i[i];
        int srow = qt * 64 + ty * 4 + i;
        float* orow = O + ((size_t)(b * S_ + srow) * HQ_ + h) * HD_ + tx * 8;
        float4 w0 = make_float4(o_acc[i][0] * inv, o_acc[i][1] * inv,
                                o_acc[i][2] * inv, o_acc[i][3] * inv);
        float4 w1 = make_float4(o_acc[i][4] * inv, o_acc[i][5] * inv,
                                o_acc[i][6] * inv, o_acc[i][7] * inv);
        *(float4*)orow = w0;
        *(float4*)(orow + 4) = w1;
    }
}

// ======================= launch =============================================
extern "C" void kernel_launch(void* const* d_in, const int* in_sizes, int n_in,
                              void* d_out, int out_size)
{
    const float* x    = (const float*)d_in[0];
    const float* cosT = (const float*)d_in[1];
    const float* sinT = (const float*)d_in[2];
    const float* Wq   = (const float*)d_in[3];
    const float* bq   = (const float*)d_in[4];
    const float* Wk   = (const float*)d_in[5];
    const float* bk   = (const float*)d_in[6];
    const float* Wv   = (const float*)d_in[7];
    const float* bv   = (const float*)d_in[8];
    const float* Wo   = (const float*)d_in[9];
    float* out = (float*)d_out;

    float *qp = nullptr, *kp = nullptr, *vp = nullptr, *ap = nullptr;
    cudaGetSymbolAddress((void**)&qp, g_q);
    cudaGetSymbolAddress((void**)&kp, g_k);
    cudaGetSymbolAddress((void**)&vp, g_v);
    cudaGetSymbolAddress((void**)&ap, g_attn);

    cudaFuncSetAttribute(attn_kernel,
                         cudaFuncAttributeMaxDynamicSharedMemorySize,
                         ATTN_SMEM_BYTES);

    const int M = B_ * S_;   // 4096 tokens

    // QKV projections
    sgemm_nt<<<dim3(HQ_ * HD_ / GBN, M / GBM), 256>>>(x, Wq, bq, qp, M, HQ_ * HD_, DIM_);
    sgemm_nt<<<dim3(HKV_ * HD_ / GBN, M / GBM), 256>>>(x, Wk, bk, kp, M, HKV_ * HD_, DIM_);
    sgemm_nt<<<dim3(HKV_ * HD_ / GBN, M / GBM), 256>>>(x, Wv, bv, vp, M, HKV_ * HD_, DIM_);

    // RoPE on q and k (in place)
    rope_kernel<<<M * HQ_, 64>>>(qp, cosT, sinT, HQ_);
    rope_kernel<<<M * HKV_, 64>>>(kp, cosT, sinT, HKV_);

    // causal flash attention
    attn_kernel<<<dim3(S_ / 64, B_ * HQ_), 256, ATTN_SMEM_BYTES>>>(qp, kp, vp, ap);

    // output projection
    sgemm_nt<<<dim3(DIM_ / GBN, M / GBM), 256>>>(ap, Wo, nullptr, out, M, DIM_, DIM_);
}

// round 3
// speedup vs baseline: 1.9112x; 1.9112x over previous
#include <cuda_runtime.h>
#include <cuda_bf16.h>
#include <math.h>
#include <stdint.h>

// Problem constants
#define B_  2
#define S_  2048
#define DIM_ 4096
#define HQ_ 32
#define HKV_ 8
#define HD_ 128
#define NREP_ 4   // HQ/HKV

// -------------------- scratch (device globals, no allocation) ---------------
__device__ float g_q[(size_t)B_ * S_ * HQ_ * HD_];    // 64 MB  [token][HQ*HD]
__device__ float g_k[(size_t)B_ * S_ * HKV_ * HD_];   // 16 MB  [token][HKV*HD]
__device__ float g_v[(size_t)B_ * S_ * HKV_ * HD_];   // 16 MB
__device__ float g_attn[(size_t)B_ * S_ * HQ_ * HD_]; // 64 MB  [token][HQ*HD]

// ======================= TF32 tensor-core NT GEMM ===========================
// C[M,N] = A[M,K] * B[N,K]^T (+ bias).  Row-major, K-contiguous operands.
// Block 128x128, BK=32, 256 threads. Warp grid 4(m) x 2(n), warp tile 32x64.
// mma.sync.m16n8k8 tf32, cp.async double buffering.
#define TBM 128
#define TBN 128
#define TBK 32
#define APAD 4
#define ALD (TBK + APAD)            // 36 floats per row
#define STAGE_ELEMS (TBM * ALD)     // one operand one stage
#define GEMM_SMEM_BYTES (4 * STAGE_ELEMS * 2 * 4)  // A+B, 2 stages... (2 ops *2 stages)

__device__ __forceinline__ uint32_t f2tf32(float f) {
    uint32_t u;
    asm volatile("cvt.rna.tf32.f32 %0, %1;" : "=r"(u) : "f"(f));
    return u;
}

__device__ __forceinline__ void cp16(void* smem_dst, const void* gsrc) {
    uint32_t d = (uint32_t)__cvta_generic_to_shared(smem_dst);
    asm volatile("cp.async.cg.shared.global [%0], [%1], 16;\n" :: "r"(d), "l"(gsrc));
}

__global__ __launch_bounds__(256) void gemm_tf32(
    const float* __restrict__ A, const float* __restrict__ Bm,
    const float* __restrict__ bias, float* __restrict__ C,
    int M, int N, int K)
{
    extern __shared__ float smem[];
    float* sA = smem;                        // [2][TBM][ALD]
    float* sB = smem + 2 * STAGE_ELEMS;      // [2][TBN][ALD]

    const int tid  = threadIdx.x;
    const int lane = tid & 31;
    const int wid  = tid >> 5;
    const int wm   = wid & 3;        // 0..3  (m)
    const int wn   = wid >> 2;       // 0..1  (n)
    const int grp  = lane >> 2;      // 0..7
    const int tcol = lane & 3;       // 0..3

    const int m0 = blockIdx.y * TBM;
    const int n0 = blockIdx.x * TBN;

    float acc[2][8][4];
#pragma unroll
    for (int i = 0; i < 2; i++)
#pragma unroll
        for (int j = 0; j < 8; j++)
#pragma unroll
            for (int t = 0; t < 4; t++) acc[i][j][t] = 0.f;

    // prefetch helper: stage buf, k-offset k0. 1024 float4 per operand.
    auto prefetch = [&](int buf, int k0) {
#pragma unroll
        for (int r = 0; r < 4; r++) {
            int idx = tid + r * 256;
            int row = idx >> 3;          // 0..127
            int c4  = (idx & 7) * 4;     // 0..28
            cp16(&sA[buf * STAGE_ELEMS + row * ALD + c4],
                 A + (size_t)(m0 + row) * K + k0 + c4);
            cp16(&sB[buf * STAGE_ELEMS + row * ALD + c4],
                 Bm + (size_t)(n0 + row) * K + k0 + c4);
        }
    };

    prefetch(0, 0);
    asm volatile("cp.async.commit_group;\n");

    const int nIter = K / TBK;
    for (int it = 0; it < nIter; it++) {
        const int buf = it & 1;
        if (it + 1 < nIter) {
            prefetch(buf ^ 1, (it + 1) * TBK);
            asm volatile("cp.async.commit_group;\n");
            asm volatile("cp.async.wait_group 1;\n");
        } else {
            asm volatile("cp.async.wait_group 0;\n");
        }
        __syncthreads();

        const float* bufA = sA + buf * STAGE_ELEMS;
        const float* bufB = sB + buf * STAGE_ELEMS;

#pragma unroll
        for (int kk = 0; kk < 4; kk++) {
            const int kb = kk * 8;
            uint32_t a[2][4], b[8][2];
#pragma unroll
            for (int mt = 0; mt < 2; mt++) {
                int r0 = wm * 32 + mt * 16 + grp;
                a[mt][0] = f2tf32(bufA[r0 * ALD + kb + tcol]);
                a[mt][1] = f2tf32(bufA[(r0 + 8) * ALD + kb + tcol]);
                a[mt][2] = f2tf32(bufA[r0 * ALD + kb + tcol + 4]);
                a[mt][3] = f2tf32(bufA[(r0 + 8) * ALD + kb + tcol + 4]);
            }
#pragma unroll
            for (int nt = 0; nt < 8; nt++) {
                int c0 = wn * 64 + nt * 8 + grp;
                b[nt][0] = f2tf32(bufB[c0 * ALD + kb + tcol]);
                b[nt][1] = f2tf32(bufB[c0 * ALD + kb + tcol + 4]);
            }
#pragma unroll
            for (int mt = 0; mt < 2; mt++)
#pragma unroll
                for (int nt = 0; nt < 8; nt++) {
                    asm volatile(
                        "mma.sync.aligned.m16n8k8.row.col.f32.tf32.tf32.f32 "
                        "{%0,%1,%2,%3}, {%4,%5,%6,%7}, {%8,%9}, {%0,%1,%2,%3};\n"
                        : "+f"(acc[mt][nt][0]), "+f"(acc[mt][nt][1]),
                          "+f"(acc[mt][nt][2]), "+f"(acc[mt][nt][3])
                        : "r"(a[mt][0]), "r"(a[mt][1]), "r"(a[mt][2]), "r"(a[mt][3]),
                          "r"(b[nt][0]), "r"(b[nt][1]));
                }
        }
        __syncthreads();
    }

    // epilogue: c0:(r, 2c) c1:(r, 2c+1) c2:(r+8, 2c) c3:(r+8, 2c+1)
#pragma unroll
    for (int mt = 0; mt < 2; mt++) {
#pragma unroll
        for (int nt = 0; nt < 8; nt++) {
            int r = m0 + wm * 32 + mt * 16 + grp;
            int c = n0 + wn * 64 + nt * 8 + tcol * 2;
            float b0 = bias ? bias[c]     : 0.f;
            float b1 = bias ? bias[c + 1] : 0.f;
            float2 v0 = make_float2(acc[mt][nt][0] + b0, acc[mt][nt][1] + b1);
            float2 v1 = make_float2(acc[mt][nt][2] + b0, acc[mt][nt][3] + b1);
            *(float2*)(C + (size_t)r * N + c) = v0;
            *(float2*)(C + (size_t)(r + 8) * N + c) = v1;
        }
    }
}

// ======================= RoPE (in place) ====================================
__global__ void rope_kernel(float* __restrict__ xh,
                            const float* __restrict__ cosT,
                            const float* __restrict__ sinT, int H)
{
    int idx = blockIdx.x;            // token*H + h
    int token = idx / H;
    int s = token % S_;
    float* p = xh + (size_t)idx * HD_;
    int d = threadIdx.x;             // 0..63
    float c0 = cosT[s * HD_ + d];
    float s0 = sinT[s * HD_ + d];
    float c1 = cosT[s * HD_ + d + 64];
    float s1 = sinT[s * HD_ + d + 64];
    float x0 = p[d];
    float x1 = p[d + 64];
    p[d]      = x0 * c0 - x1 * s0;
    p[d + 64] = x1 * c1 + x0 * s1;
}

// ======================= Flash attention (fp32) =============================
#define ATTN_SMEM_BYTES ((64 * 128 + 64 * 128 + 64 * 64) * 4)

__global__ __launch_bounds__(256) void attn_kernel(
    const float* __restrict__ Q, const float* __restrict__ Kg,
    const float* __restrict__ Vg, float* __restrict__ O)
{
    extern __shared__ float smem[];
    float* Qs  = smem;                 // 64*128
    float* KVs = smem + 64 * 128;      // 64*128 (K then V)
    float* Ps  = smem + 2 * 64 * 128;  // 64*64

    const int qt = blockIdx.x;
    const int bh = blockIdx.y;
    const int b  = bh / HQ_;
    const int h  = bh % HQ_;
    const int kh = h / NREP_;

    const int tid = threadIdx.x;
    const int tx = tid & 15;
    const int ty = tid >> 4;

    const float scaling = 0.08838834764831845f;  // 1/sqrt(128)

    const float* qbase = Q + ((size_t)(b * S_ + qt * 64) * HQ_ + h) * HD_;
#pragma unroll
    for (int r = 0; r < 8; r++) {
        int idx = tid + r * 256;
        int row = idx >> 5;
        int c4  = idx & 31;
        float4 v = *(const float4*)(qbase + (size_t)row * HQ_ * HD_ + c4 * 4);
        *(float4*)&Qs[row * 128 + c4 * 4] = v;
    }

    float m_i[4], l_i[4], o_acc[4][8];
#pragma unroll
    for (int i = 0; i < 4; i++) {
        m_i[i] = -1e30f;
        l_i[i] = 0.f;
#pragma unroll
        for (int j = 0; j < 8; j++) o_acc[i][j] = 0.f;
    }
    __syncthreads();

    const float* kbase = Kg + (size_t)b * S_ * HKV_ * HD_ + (size_t)kh * HD_;
    const float* vbase = Vg + (size_t)b * S_ * HKV_ * HD_ + (size_t)kh * HD_;
    float4* K4 = (float4*)KVs;
    float4* V4 = (float4*)KVs;

    for (int kt = 0; kt <= qt; kt++) {
#pragma unroll
        for (int r = 0; r < 8; r++) {
            int idx = tid + r * 256;
            int col = idx >> 5;
            int k4  = idx & 31;
            float4 v = *(const float4*)(kbase +
                        (size_t)(kt * 64 + col) * HKV_ * HD_ + k4 * 4);
            K4[col * 32 + (k4 ^ (col & 31))] = v;
        }
        __syncthreads();

        float sacc[4][4];
#pragma unroll
        for (int i = 0; i < 4; i++)
#pragma unroll
            for (int j = 0; j < 4; j++) sacc[i][j] = 0.f;

#pragma unroll 4
        for (int k4 = 0; k4 < 32; k4++) {
            float4 a[4], bb[4];
#pragma unroll
            for (int i = 0; i < 4; i++)
                a[i] = *(const float4*)&Qs[(ty * 4 + i) * 128 + k4 * 4];
#pragma unroll
            for (int j = 0; j < 4; j++) {
                int col = tx * 4 + j;
                bb[j] = K4[col * 32 + (k4 ^ (col & 31))];
            }
#pragma unroll
            for (int i = 0; i < 4; i++)
#pragma unroll
                for (int j = 0; j < 4; j++)
                    sacc[i][j] += a[i].x * bb[j].x + a[i].y * bb[j].y +
                                  a[i].z * bb[j].z + a[i].w * bb[j].w;
        }

        const bool diag = (kt == qt);
#pragma unroll
        for (int i = 0; i < 4; i++)
#pragma unroll
            for (int j = 0; j < 4; j++) {
                float s = sacc[i][j] * scaling;
                if (diag && (tx * 4 + j) > (ty * 4 + i)) s = -1e30f;
                sacc[i][j] = s;
            }

#pragma unroll
        for (int i = 0; i < 4; i++) {
            float rmax = fmaxf(fmaxf(sacc[i][0], sacc[i][1]),
                               fmaxf(sacc[i][2], sacc[i][3]));
#pragma unroll
            for (int off = 8; off; off >>= 1)
                rmax = fmaxf(rmax, __shfl_xor_sync(0xffffffffu, rmax, off));
            float mnew = fmaxf(m_i[i], rmax);
            float corr = __expf(m_i[i] - mnew);
            m_i[i] = mnew;
            float rsum = 0.f;
#pragma unroll
            for (int j = 0; j < 4; j++) {
                float p = __expf(sacc[i][j] - mnew);
                sacc[i][j] = p;
                rsum += p;
            }
#pragma unroll
            for (int off = 8; off; off >>= 1)
                rsum += __shfl_xor_sync(0xffffffffu, rsum, off);
            l_i[i] = l_i[i] * corr + rsum;
#pragma unroll
            for (int j = 0; j < 8; j++) o_acc[i][j] *= corr;
            *(float4*)&Ps[(ty * 4 + i) * 64 + tx * 4] =
                make_float4(sacc[i][0], sacc[i][1], sacc[i][2], sacc[i][3]);
        }
        __syncthreads();

#pragma unroll
        for (int r = 0; r < 8; r++) {
            int idx = tid + r * 256;
            int row = idx >> 5;
            int c4  = idx & 31;
            V4[row * 32 + c4] = *(const float4*)(vbase +
                        (size_t)(kt * 64 + row) * HKV_ * HD_ + c4 * 4);
        }
        __syncthreads();

#pragma unroll 4
        for (int kk = 0; kk < 64; kk++) {
            float p0 = Ps[(ty * 4 + 0) * 64 + kk];
            float p1 = Ps[(ty * 4 + 1) * 64 + kk];
            float p2 = Ps[(ty * 4 + 2) * 64 + kk];
            float p3 = Ps[(ty * 4 + 3) * 64 + kk];
            float4 v0 = V4[kk * 32 + tx * 2];
            float4 v1 = V4[kk * 32 + tx * 2 + 1];
            float pv[4] = {p0, p1, p2, p3};
#pragma unroll
            for (int i = 0; i < 4; i++) {
                o_acc[i][0] += pv[i] * v0.x; o_acc[i][1] += pv[i] * v0.y;
                o_acc[i][2] += pv[i] * v0.z; o_acc[i][3] += pv[i] * v0.w;
                o_acc[i][4] += pv[i] * v1.x; o_acc[i][5] += pv[i] * v1.y;
                o_acc[i][6] += pv[i] * v1.z; o_acc[i][7] += pv[i] * v1.w;
            }
        }
        __syncthreads();
    }

#pragma unroll
    for (int i = 0; i < 4; i++) {
        float inv = 1.f / l_i[i];
        int srow = qt * 64 + ty * 4 + i;
        float* orow = O + ((size_t)(b * S_ + srow) * HQ_ + h) * HD_ + tx * 8;
        float4 w0 = make_float4(o_acc[i][0] * inv, o_acc[i][1] * inv,
                                o_acc[i][2] * inv, o_acc[i][3] * inv);
        float4 w1 = make_float4(o_acc[i][4] * inv, o_acc[i][5] * inv,
                                o_acc[i][6] * inv, o_acc[i][7] * inv);
        *(float4*)orow = w0;
        *(float4*)(orow + 4) = w1;
    }
}

// ======================= launch =============================================
extern "C" void kernel_launch(void* const* d_in, const int* in_sizes, int n_in,
                              void* d_out, int out_size)
{
    const float* x    = (const float*)d_in[0];
    const float* cosT = (const float*)d_in[1];
    const float* sinT = (const float*)d_in[2];
    const float* Wq   = (const float*)d_in[3];
    const float* bq   = (const float*)d_in[4];
    const float* Wk   = (const float*)d_in[5];
    const float* bk   = (const float*)d_in[6];
    const float* Wv   = (const float*)d_in[7];
    const float* bv   = (const float*)d_in[8];
    const float* Wo   = (const float*)d_in[9];
    float* out = (float*)d_out;

    float *qp = nullptr, *kp = nullptr, *vp = nullptr, *ap = nullptr;
    cudaGetSymbolAddress((void**)&qp, g_q);
    cudaGetSymbolAddress((void**)&kp, g_k);
    cudaGetSymbolAddress((void**)&vp, g_v);
    cudaGetSymbolAddress((void**)&ap, g_attn);

    static int attr_done = 0;
    if (!attr_done) {
        cudaFuncSetAttribute(attn_kernel,
                             cudaFuncAttributeMaxDynamicSharedMemorySize,
                             ATTN_SMEM_BYTES);
        cudaFuncSetAttribute(gemm_tf32,
                             cudaFuncAttributeMaxDynamicSharedMemorySize,
                             GEMM_SMEM_BYTES);
        attr_done = 1;
    }

    const int M = B_ * S_;   // 4096 tokens

    // QKV projections (tf32 tensor cores)
    gemm_tf32<<<dim3(HQ_ * HD_ / TBN, M / TBM), 256, GEMM_SMEM_BYTES>>>(
        x, Wq, bq, qp, M, HQ_ * HD_, DIM_);
    gemm_tf32<<<dim3(HKV_ * HD_ / TBN, M / TBM), 256, GEMM_SMEM_BYTES>>>(
        x, Wk, bk, kp, M, HKV_ * HD_, DIM_);
    gemm_tf32<<<dim3(HKV_ * HD_ / TBN, M / TBM), 256, GEMM_SMEM_BYTES>>>(
        x, Wv, bv, vp, M, HKV_ * HD_, DIM_);

    // RoPE on q and k (in place)
    rope_kernel<<<M * HQ_, 64>>>(qp, cosT, sinT, HQ_);
    rope_kernel<<<M * HKV_, 64>>>(kp, cosT, sinT, HKV_);

    // causal flash attention (fp32)
    attn_kernel<<<dim3(S_ / 64, B_ * HQ_), 256, ATTN_SMEM_BYTES>>>(qp, kp, vp, ap);

    // output projection (tf32 tensor cores)
    gemm_tf32<<<dim3(DIM_ / TBN, M / TBM), 256, GEMM_SMEM_BYTES>>>(
        ap, Wo, nullptr, out, M, DIM_, DIM_);
}